// round 14
// baseline (speedup 1.0000x reference)
#include <cuda_runtime.h>

// SimpleLSTM: B=4096, T=256, I=16, H=32, O=1 (fp32)
// R14: gate-split warp pairs -> 4 warps/SMSP.
// CTA = 512 thr (16 warps) = 8 pairs (p = wid&7, member m = wid>>3).
// Member 0 owns gates {i,f}, member 1 owns {g,o}: W_hh regs halve (64/warp)
// -> 16 warps/SM. Pair shares NB batches (heavy CTAs: pairs 0-3 NB=4,
// pairs 4-7 NB=3 -> 7 batches/SMSP, R12 balance). Per step: each member
// accumulates + activates its 2 gates, exchanges via smem (named bar),
// updates c,h for its half of the batches, h broadcast (named bar).
// x: 3-slot cp.async ring (distance 2), managed by member 0.

#define BB 4096
#define TT 256
#define II 16
#define HH 32
#define THREADS 512
#define NCTA 148
#define NHEAVY 136

typedef unsigned long long ull;

__device__ __forceinline__ void ffma2(ull& acc, ull a, ull b) {
    asm("fma.rn.f32x2 %0, %1, %2, %0;" : "+l"(acc) : "l"(a), "l"(b));
}
__device__ __forceinline__ void ffma2_init(ull& acc, ull a, ull b, ull addend) {
    asm("fma.rn.f32x2 %0, %1, %2, %3;" : "=l"(acc) : "l"(a), "l"(b), "l"(addend));
}
__device__ __forceinline__ float hadd2(ull v) {
    float lo, hi;
    asm("mov.b64 {%0, %1}, %2;" : "=f"(lo), "=f"(hi) : "l"(v));
    return lo + hi;
}
__device__ __forceinline__ ull pack2(float lo, float hi) {
    ull r;
    asm("mov.b64 %0, {%1, %2};" : "=l"(r) : "f"(lo), "f"(hi));
    return r;
}
__device__ __forceinline__ float tanh_a(float v) {
    float r;
    asm("tanh.approx.f32 %0, %1;" : "=f"(r) : "f"(v));
    return r;
}
__device__ __forceinline__ void cp_async16(void* smem_dst, const void* gsrc) {
    unsigned saddr = (unsigned)__cvta_generic_to_shared(smem_dst);
    asm volatile("cp.async.ca.shared.global [%0], [%1], 16;" :: "r"(saddr), "l"(gsrc));
}
__device__ __forceinline__ void cp_commit() {
    asm volatile("cp.async.commit_group;" ::: "memory");
}
__device__ __forceinline__ void cp_wait1() {
    asm volatile("cp.async.wait_group 1;" ::: "memory");
}
__device__ __forceinline__ void pbar(int p) {
    asm volatile("bar.sync %0, 64;" :: "r"(p + 1) : "memory");
}

// shared state
__shared__ float4 g_wihA[II / 2][HH];       // (0.5Wi, 0.5Wf) pairs per lane
__shared__ float4 g_wihB[II / 2][HH];       // (Wg, 0.5Wo)
__shared__ float  g_h[8][2][4][HH];         // [pair][buf][bb][lane]
__shared__ float2 g_ex[8][2][4][HH];        // [pair][member][bb][lane]
__shared__ float  g_x[8][3][4][II];         // [pair][slot][bb][i]

// ---- one step. M = member (0: gates i,f; 1: g,o). RB = h read buffer. ----
template <int NB, int M, int RB>
__device__ __forceinline__ void lstm_step(
    const int j, const int p,
    const ulonglong2* wih,                  // member's x-proj weights (smem)
    const ull (&whh2)[2][HH / 2],           // member's 2-gate W_hh (regs)
    const ull bias0, const ull bias1,
    float (&g0a)[NB], float (&g1a)[NB],     // own activated gates (out)
    float* cown, float* hown,               // own-batch state
    int xsl, int nsl,
    const float* gsrc_next, int cb, int cc)
{
    ull a0[NB], a1[NB];

    // ---- x-proj (bias fused at i2==0) ----
    #pragma unroll
    for (int i2 = 0; i2 < 8; i2++) {
        ulonglong2 w = wih[i2 * 32];
        #pragma unroll
        for (int bb = 0; bb < NB; bb++) {
            ull xp = reinterpret_cast<const ull*>(&g_x[p][xsl][bb][0])[i2];
            if (i2 == 0) {
                ffma2_init(a0[bb], w.x, xp, bias0);
                ffma2_init(a1[bb], w.y, xp, bias1);
            } else {
                ffma2(a0[bb], w.x, xp);
                ffma2(a1[bb], w.y, xp);
            }
        }
    }

    // ---- recurrent matvec (register weights) ----
    #pragma unroll
    for (int kk = 0; kk < 8; kk++) {
        #pragma unroll
        for (int bb = 0; bb < NB; bb++) {
            ulonglong2 hq = reinterpret_cast<const ulonglong2*>(&g_h[p][RB][bb][0])[kk];
            ffma2(a0[bb], whh2[0][2 * kk], hq.x); ffma2(a0[bb], whh2[0][2 * kk + 1], hq.y);
            ffma2(a1[bb], whh2[1][2 * kk], hq.x); ffma2(a1[bb], whh2[1][2 * kk + 1], hq.y);
        }
    }

    // ---- own-gate activations + publish ----
    #pragma unroll
    for (int bb = 0; bb < NB; bb++) {
        float t0 = tanh_a(hadd2(a0[bb]));
        float t1 = tanh_a(hadd2(a1[bb]));
        g0a[bb] = (M == 0) ? fmaf(t0, 0.5f, 0.5f) : t0;   // sigma(i) or tanh(g)
        g1a[bb] = fmaf(t1, 0.5f, 0.5f);                   // sigma(f) or sigma(o)
        g_ex[p][M][bb][j] = make_float2(g0a[bb], g1a[bb]);
    }

    // ---- x ring (member 0): issue cp(t+2), guarantee x(t+1) done ----
    if (M == 0) {
        if (j < 4 * NB) cp_async16(&g_x[p][nsl][cb][cc * 4], gsrc_next);
        cp_commit();
        cp_wait1();
    }
    pbar(p);   // gates + x(t+1) visible pair-wide

    // ---- cross gates + state update for own batches (bb & 1) == M ----
    constexpr int NOWN = (M == 0) ? (NB + 1) / 2 : NB / 2;
    #pragma unroll
    for (int ob = 0; ob < NOWN; ob++) {
        const int bb = 2 * ob + M;
        float2 og = g_ex[p][1 - M][bb][j];
        float gi, gf, gg, go;
        if (M == 0) { gi = g0a[bb]; gf = g1a[bb]; gg = og.x; go = og.y; }
        else        { gi = og.x;    gf = og.y;    gg = g0a[bb]; go = g1a[bb]; }
        float cc2 = fmaf(gf, cown[ob], gi * gg);
        cown[ob] = cc2;
        float hh = go * tanh_a(cc2);
        hown[ob] = hh;
        g_h[p][RB ^ 1][bb][j] = hh;
    }
    pbar(p);   // h(t) visible pair-wide
}

template <int NB, int M>
__device__ __forceinline__ void lstm_run(
    const int j, const int p, const int b0,
    const float* __restrict__ x,
    const float* __restrict__ W_hh,
    const float* __restrict__ b_ih, const float* __restrict__ b_hh,
    const float* __restrict__ W_fc, const float* __restrict__ b_fc,
    float* __restrict__ out)
{
    // ---- member's 2-gate W_hh into registers (64 regs) ----
    const float s0 = (M == 0) ? 0.5f : 1.0f;   // i or g
    ull whh2[2][HH / 2];
    {
        const float* w0 = W_hh + ((2 * M + 0) * HH + j) * HH;
        const float* w1 = W_hh + ((2 * M + 1) * HH + j) * HH;
        #pragma unroll
        for (int k2 = 0; k2 < HH / 2; k2++) {
            whh2[0][k2] = pack2(s0 * w0[2 * k2], s0 * w0[2 * k2 + 1]);
            whh2[1][k2] = pack2(0.5f * w1[2 * k2], 0.5f * w1[2 * k2 + 1]);
        }
    }
    const ull bias0 = pack2(s0 * (b_ih[(2 * M + 0) * HH + j] + b_hh[(2 * M + 0) * HH + j]), 0.0f);
    const ull bias1 = pack2(0.5f * (b_ih[(2 * M + 1) * HH + j] + b_hh[(2 * M + 1) * HH + j]), 0.0f);

    const ulonglong2* wih = reinterpret_cast<const ulonglong2*>(
        (M == 0) ? &g_wihA[0][j] : &g_wihB[0][j]);

    const int cb = j >> 2, cc = j & 3;
    const float* gsrc = x + (long)(b0 + cb) * TT * II + cc * 4;

    constexpr int NOWN = (M == 0) ? (NB + 1) / 2 : NB / 2;
    float cown[NOWN > 0 ? NOWN : 1], hown[NOWN > 0 ? NOWN : 1];
    #pragma unroll
    for (int ob = 0; ob < NOWN; ob++) { cown[ob] = 0.f; hown[ob] = 0.f; }
    float g0a[NB], g1a[NB];

    // ---- prologue: h(-1)=0, x(0), x(1) prefetched ----
    if (M == 0) {
        #pragma unroll
        for (int bb = 0; bb < NB; bb++) g_h[p][0][bb][j] = 0.0f;
        if (j < 4 * NB) cp_async16(&g_x[p][0][cb][cc * 4], gsrc);
        cp_commit();
        if (j < 4 * NB) cp_async16(&g_x[p][1][cb][cc * 4], gsrc + II);
        cp_commit();
        cp_wait1();            // x(0) resident
    }
    pbar(p);                   // h(-1) + x(0) visible

    int xsl = 0, nsl = 2;      // read slot t%3, cp slot (t+2)%3
    #pragma unroll 1
    for (int t = 0; t < TT; t += 2) {
        const int t2a = (t + 2 < TT) ? t + 2 : TT - 1;
        lstm_step<NB, M, 0>(j, p, wih, whh2, bias0, bias1, g0a, g1a,
                            cown, hown, xsl, nsl, gsrc + (long)t2a * II, cb, cc);
        xsl = (xsl == 2) ? 0 : xsl + 1;
        nsl = (nsl == 2) ? 0 : nsl + 1;
        const int t2b = (t + 3 < TT) ? t + 3 : TT - 1;
        lstm_step<NB, M, 1>(j, p, wih, whh2, bias0, bias1, g0a, g1a,
                            cown, hown, xsl, nsl, gsrc + (long)t2b * II, cb, cc);
        xsl = (xsl == 2) ? 0 : xsl + 1;
        nsl = (nsl == 2) ? 0 : nsl + 1;
    }

    // ---- final FC (O=1) for own batches ----
    float wf = W_fc[j];
    #pragma unroll
    for (int ob = 0; ob < NOWN; ob++) {
        float v = hown[ob] * wf;
        #pragma unroll
        for (int off = 16; off; off >>= 1)
            v += __shfl_xor_sync(0xffffffffu, v, off);
        if (j == 0)
            out[b0 + 2 * ob + M] = v + b_fc[0];
    }
}

__global__ void __launch_bounds__(THREADS, 1)
lstm_pair_kernel(const float* __restrict__ x,
                 const float* __restrict__ W_ih,
                 const float* __restrict__ W_hh,
                 const float* __restrict__ b_ih,
                 const float* __restrict__ b_hh,
                 const float* __restrict__ W_fc,
                 const float* __restrict__ b_fc,
                 float* __restrict__ out)
{
    const int tid = threadIdx.x;
    const int wid = tid >> 5;
    const int j   = tid & 31;
    const int p   = wid & 7;     // pair
    const int m   = wid >> 3;    // member

    // ---- stage W_ih (once per block), gate-scaled ----
    for (int idx = tid; idx < (II / 2) * HH; idx += THREADS) {
        int i2 = idx >> 5, jj = idx & 31;
        g_wihA[i2][jj] = make_float4(0.5f * W_ih[(0 * HH + jj) * II + 2 * i2],
                                     0.5f * W_ih[(0 * HH + jj) * II + 2 * i2 + 1],
                                     0.5f * W_ih[(1 * HH + jj) * II + 2 * i2],
                                     0.5f * W_ih[(1 * HH + jj) * II + 2 * i2 + 1]);
        g_wihB[i2][jj] = make_float4(W_ih[(2 * HH + jj) * II + 2 * i2],
                                     W_ih[(2 * HH + jj) * II + 2 * i2 + 1],
                                     0.5f * W_ih[(3 * HH + jj) * II + 2 * i2],
                                     0.5f * W_ih[(3 * HH + jj) * II + 2 * i2 + 1]);
    }
    __syncthreads();

    // ---- pair -> batch mapping (R12 SMSP balance) ----
    const int cta = blockIdx.x;
    if (cta < NHEAVY) {
        const int base = cta * 28;
        if (p < 4) {
            const int b0 = base + p * 4;                    // NB = 4
            if (m == 0) lstm_run<4, 0>(j, p, b0, x, W_hh, b_ih, b_hh, W_fc, b_fc, out);
            else        lstm_run<4, 1>(j, p, b0, x, W_hh, b_ih, b_hh, W_fc, b_fc, out);
        } else {
            const int b0 = base + 16 + (p - 4) * 3;         // NB = 3
            if (m == 0) lstm_run<3, 0>(j, p, b0, x, W_hh, b_ih, b_hh, W_fc, b_fc, out);
            else        lstm_run<3, 1>(j, p, b0, x, W_hh, b_ih, b_hh, W_fc, b_fc, out);
        }
    } else {
        const int b0 = NHEAVY * 28 + (cta - NHEAVY) * 24 + p * 3;   // NB = 3
        if (m == 0) lstm_run<3, 0>(j, p, b0, x, W_hh, b_ih, b_hh, W_fc, b_fc, out);
        else        lstm_run<3, 1>(j, p, b0, x, W_hh, b_ih, b_hh, W_fc, b_fc, out);
    }
}

extern "C" void kernel_launch(void* const* d_in, const int* in_sizes, int n_in,
                              void* d_out, int out_size) {
    (void)in_sizes; (void)n_in; (void)out_size;
    const float* x    = (const float*)d_in[0];
    const float* W_ih = (const float*)d_in[1];
    const float* W_hh = (const float*)d_in[2];
    const float* b_ih = (const float*)d_in[3];
    const float* b_hh = (const float*)d_in[4];
    const float* W_fc = (const float*)d_in[5];
    const float* b_fc = (const float*)d_in[6];
    float* out = (float*)d_out;

    dim3 grid(NCTA);
    dim3 block(THREADS);
    lstm_pair_kernel<<<grid, block>>>(x, W_ih, W_hh, b_ih, b_hh, W_fc, b_fc, out);
}

// round 16
// speedup vs baseline: 1.2926x; 1.2926x over previous
#include <cuda_runtime.h>
#include <cuda_bf16.h>
#include <cstdint>

// SimpleLSTM: B=4096, T=256, I=16, H=32, O=1 (fp32)
// R16: HMMA (mma.sync.m16n8k16, arch-neutral) recurrence.
// CTA = 16 batches, 128 thr (4 warps). Warp w's M=32 rows map to
// (gate = m/8, unit = 8w + m%8): after the MMA each thread holds ALL 4
// gates of unit u = 8w + lane/4 for its 8 batches -> cell update fully
// in registers, no exchange. A (weights, bf16 hi/lo, gate-scaled 0.5 for
// i,f,o) lives in registers (48 regs). B = [h(0:31) | xA(32:47) | xB(48:63)]
// in smem rows [batch][72] bf16 (stride 144B -> conflict-free b-frags).
// 3 compensation segments: Whi*vhi + Whi*vlo + Wlo*vhi (~fp32 accurate).
// x pre-split hi/lo by prep kernel, cp.async double-buffered.

#define BB 4096
#define TT 256
#define II 16
#define HH 32
#define NB 16
#define NCTA (BB / NB)    // 256
#define THREADS 128
#define KS 72             // padded K stride (bank-clean: 144B = 36 words)

__device__ uint4 g_xpk[(long)BB * TT * 4];   // [b*T+t] -> {hi0,hi1,lo0,lo1} 16B each

__device__ __forceinline__ float tanh_a(float v) {
    float r; asm("tanh.approx.f32 %0, %1;" : "=f"(r) : "f"(v)); return r;
}
__device__ __forceinline__ void cp_async16(void* smem_dst, const void* gsrc) {
    unsigned a = (unsigned)__cvta_generic_to_shared(smem_dst);
    asm volatile("cp.async.ca.shared.global [%0], [%1], 16;" :: "r"(a), "l"(gsrc));
}
__device__ __forceinline__ void cp_commit() {
    asm volatile("cp.async.commit_group;" ::: "memory");
}
__device__ __forceinline__ void cp_wait0() {
    asm volatile("cp.async.wait_group 0;" ::: "memory");
}
// D(f32) += A(bf16) * B(bf16), m16n8k16, A row-major, B col-major
__device__ __forceinline__ void mma_bf16(float* d, const uint32_t* a, const uint32_t* b) {
    asm volatile(
        "mma.sync.aligned.m16n8k16.row.col.f32.bf16.bf16.f32 "
        "{%0,%1,%2,%3}, {%4,%5,%6,%7}, {%8,%9}, {%0,%1,%2,%3};"
        : "+f"(d[0]), "+f"(d[1]), "+f"(d[2]), "+f"(d[3])
        : "r"(a[0]), "r"(a[1]), "r"(a[2]), "r"(a[3]), "r"(b[0]), "r"(b[1]));
}
__device__ __forceinline__ uint32_t pack_bf2(__nv_bfloat16 e0, __nv_bfloat16 e1) {
    uint32_t r;
    uint16_t u0 = *reinterpret_cast<uint16_t*>(&e0);
    uint16_t u1 = *reinterpret_cast<uint16_t*>(&e1);
    r = (uint32_t)u0 | ((uint32_t)u1 << 16);
    return r;
}

// ---------------- prep: x -> bf16 hi/lo ----------------
__global__ void __launch_bounds__(256)
prep_x_kernel(const float* __restrict__ x) {
    const long idx = (long)blockIdx.x * 256 + threadIdx.x;   // b*T + t
    if (idx >= (long)BB * TT) return;
    const float4* src = reinterpret_cast<const float4*>(x + idx * II);
    float4 v0 = src[0], v1 = src[1], v2 = src[2], v3 = src[3];
    float v[16] = {v0.x, v0.y, v0.z, v0.w, v1.x, v1.y, v1.z, v1.w,
                   v2.x, v2.y, v2.z, v2.w, v3.x, v3.y, v3.z, v3.w};
    __nv_bfloat16 hi[16], lo[16];
    #pragma unroll
    for (int i = 0; i < 16; i++) {
        hi[i] = __float2bfloat16(v[i]);
        lo[i] = __float2bfloat16(v[i] - __bfloat162float(hi[i]));
    }
    uint4* dst = g_xpk + idx * 4;
    dst[0] = *reinterpret_cast<uint4*>(&hi[0]);
    dst[1] = *reinterpret_cast<uint4*>(&hi[8]);
    dst[2] = *reinterpret_cast<uint4*>(&lo[0]);
    dst[3] = *reinterpret_cast<uint4*>(&lo[8]);
}

// ---------------- main kernel ----------------
__global__ void __launch_bounds__(THREADS, 2)
lstm_hmma_kernel(const float* __restrict__ W_ih,   // [4H,I]
                 const float* __restrict__ W_hh,   // [4H,H]
                 const float* __restrict__ b_ih,   // [4H]
                 const float* __restrict__ b_hh,   // [4H]
                 const float* __restrict__ W_fc,   // [1,H]
                 const float* __restrict__ b_fc,   // [1]
                 float* __restrict__ out)          // [B,1]
{
    __shared__ __align__(16) __nv_bfloat16 sVh[NB][KS];   // B hi: h | xA | xB | pad
    __shared__ __align__(16) __nv_bfloat16 sVl[NB][KS];   // B lo
    __shared__ float sRed[4][NB];

    const int tid = threadIdx.x;
    const int w   = tid >> 5;
    const int l   = tid & 31;
    const int lr  = l >> 2;     // 0..7
    const int lc  = l & 3;      // 0..3
    const int b0  = blockIdx.x * NB;

    // ---- zero sV (h rows = 0 initial state; pad = 0) ----
    for (int i = tid; i < NB * KS * 2 * 2 / 16; i += THREADS)
        reinterpret_cast<uint4*>(sVh)[i] = make_uint4(0, 0, 0, 0);
    // (sVh and sVl are contiguous in smem declaration order; the loop above
    // covers NB*KS*2 bf16 * 2 arrays = NB*KS*2*2 bytes / 16 per uint4)

    // ---- A fragments in registers: warp w, m_local -> gate=m/8, unit=8w+m%8 ----
    // frag part p: row += (p&1)*8, col += (p&2)*4 (i.e. +8 when p>=2)
    uint32_t Ahi[2][3][4], Alo[2][3][4];
    #pragma unroll
    for (int mt = 0; mt < 2; mt++)
        #pragma unroll
        for (int kc = 0; kc < 3; kc++)
            #pragma unroll
            for (int p = 0; p < 4; p++) {
                int m    = mt * 16 + lr + ((p & 1) ? 8 : 0);
                int gate = m >> 3;
                int unit = 8 * w + (m & 7);
                int grow = gate * HH + unit;
                int k    = kc * 16 + lc * 2 + ((p & 2) ? 8 : 0);
                float s  = (gate == 2) ? 1.0f : 0.5f;     // sigmoid fold
                float v0 = s * ((k < HH) ? W_hh[grow * HH + k]
                                         : W_ih[grow * II + (k - HH)]);
                float v1 = s * ((k + 1 < HH || k >= HH)
                                 ? ((k + 1 < HH) ? W_hh[grow * HH + k + 1]
                                                 : W_ih[grow * II + (k + 1 - HH)])
                                 : W_ih[grow * II + 0]);  // unreachable (k even)
                __nv_bfloat16 h0 = __float2bfloat16(v0);
                __nv_bfloat16 h1 = __float2bfloat16(v1);
                Ahi[mt][kc][p] = pack_bf2(h0, h1);
                Alo[mt][kc][p] = pack_bf2(__float2bfloat16(v0 - __bfloat162float(h0)),
                                          __float2bfloat16(v1 - __bfloat162float(h1)));
            }

    // biases for this thread's unit u = 8w+lr, one per gate (gate-scaled)
    const int u = 8 * w + lr;
    float biasg[4];
    #pragma unroll
    for (int g = 0; g < 4; g++) {
        float s = (g == 2) ? 1.0f : 0.5f;
        biasg[g] = s * (b_ih[g * HH + u] + b_hh[g * HH + u]);
    }

    // ---- x(t=0) -> slot 0 (k 32..47) ----
    if (tid < 64) {
        int bat = tid >> 2, q = tid & 3;
        const uint4* src = g_xpk + ((long)(b0 + bat) * TT + 0) * 4 + q;
        char* dst = (q < 2) ? (char*)&sVh[bat][32] + q * 16
                            : (char*)&sVl[bat][32] + (q - 2) * 16;
        cp_async16(dst, src);
    }
    cp_commit();
    cp_wait0();
    __syncthreads();

    float cc[4] = {0.f, 0.f, 0.f, 0.f};   // c for (nt, j)
    float hh4[4];

    #pragma unroll 1
    for (int t = 0; t < TT; t++) {
        const int kx = 32 + 16 * (t & 1);

        // ---- load B fragments (h chunks + current x chunk) ----
        uint32_t bh[2][3][2], bl[2][3][2];
        #pragma unroll
        for (int nt = 0; nt < 2; nt++) {
            const int n = nt * 8 + lr;
            #pragma unroll
            for (int kc = 0; kc < 3; kc++) {
                const int kb = (kc < 2) ? kc * 16 : kx;
                const __nv_bfloat16* ph = &sVh[n][kb + lc * 2];
                const __nv_bfloat16* pl = &sVl[n][kb + lc * 2];
                bh[nt][kc][0] = *reinterpret_cast<const uint32_t*>(ph);
                bh[nt][kc][1] = *reinterpret_cast<const uint32_t*>(ph + 8);
                bl[nt][kc][0] = *reinterpret_cast<const uint32_t*>(pl);
                bl[nt][kc][1] = *reinterpret_cast<const uint32_t*>(pl + 8);
            }
        }
        __syncthreads();   // all warps captured h(t-1)+x(t): h region now writable

        // ---- prefetch x(t+1) into the other slot ----
        {
            const int tn = (t + 1 < TT) ? t + 1 : TT - 1;
            const int xo = 32 + 16 * ((t + 1) & 1);
            if (tid < 64) {
                int bat = tid >> 2, q = tid & 3;
                const uint4* src = g_xpk + ((long)(b0 + bat) * TT + tn) * 4 + q;
                char* dst = (q < 2) ? (char*)&sVh[bat][xo] + q * 16
                                    : (char*)&sVl[bat][xo] + (q - 2) * 16;
                cp_async16(dst, src);
            }
            cp_commit();
        }

        // ---- MMAs: acc init with bias, 3 segments x 2mt x 2nt x 3kc ----
        float acc[2][2][4];
        #pragma unroll
        for (int mt = 0; mt < 2; mt++)
            #pragma unroll
            for (int nt = 0; nt < 2; nt++) {
                acc[mt][nt][0] = biasg[mt * 2];     // gate mt*2   (rows lr)
                acc[mt][nt][1] = biasg[mt * 2];
                acc[mt][nt][2] = biasg[mt * 2 + 1]; // gate mt*2+1 (rows lr+8)
                acc[mt][nt][3] = biasg[mt * 2 + 1];
            }
        #pragma unroll
        for (int kc = 0; kc < 3; kc++)
            #pragma unroll
            for (int mt = 0; mt < 2; mt++)
                #pragma unroll
                for (int nt = 0; nt < 2; nt++) {
                    mma_bf16(acc[mt][nt], Ahi[mt][kc], bh[nt][kc]);   // hi*hi
                    mma_bf16(acc[mt][nt], Ahi[mt][kc], bl[nt][kc]);   // hi*lo
                    mma_bf16(acc[mt][nt], Alo[mt][kc], bh[nt][kc]);   // lo*hi
                }

        // ---- cell update (all 4 gates in-register), write h hi/lo ----
        #pragma unroll
        for (int nt = 0; nt < 2; nt++)
            #pragma unroll
            for (int j = 0; j < 2; j++) {
                float gi = fmaf(tanh_a(acc[0][nt][j]),     0.5f, 0.5f);
                float gf = fmaf(tanh_a(acc[0][nt][2 + j]), 0.5f, 0.5f);
                float gg = tanh_a(acc[1][nt][j]);
                float go = fmaf(tanh_a(acc[1][nt][2 + j]), 0.5f, 0.5f);
                const int s = nt * 2 + j;
                cc[s] = fmaf(gf, cc[s], gi * gg);
                float hv = go * tanh_a(cc[s]);
                hh4[s] = hv;
                const int bat = nt * 8 + lc * 2 + j;
                __nv_bfloat16 hi = __float2bfloat16(hv);
                sVh[bat][u] = hi;
                sVl[bat][u] = __float2bfloat16(hv - __bfloat162float(hi));
            }

        cp_wait0();
        __syncthreads();   // h(t) + x(t+1) visible
    }

    // ---- final FC (O=1): reduce over units ----
    float wfc = W_fc[u];
    float p4[4];
    #pragma unroll
    for (int s = 0; s < 4; s++) p4[s] = hh4[s] * wfc;
    #pragma unroll
    for (int off = 4; off < 32; off <<= 1) {
        #pragma unroll
        for (int s = 0; s < 4; s++)
            p4[s] += __shfl_xor_sync(0xffffffffu, p4[s], off);
    }
    if (lr == 0) {
        #pragma unroll
        for (int nt = 0; nt < 2; nt++)
            #pragma unroll
            for (int j = 0; j < 2; j++)
                sRed[w][nt * 8 + lc * 2 + j] = p4[nt * 2 + j];
    }
    __syncthreads();
    if (tid < NB)
        out[b0 + tid] = sRed[0][tid] + sRed[1][tid] + sRed[2][tid] + sRed[3][tid]
                      + b_fc[0];
}

extern "C" void kernel_launch(void* const* d_in, const int* in_sizes, int n_in,
                              void* d_out, int out_size) {
    (void)in_sizes; (void)n_in; (void)out_size;
    const float* x    = (const float*)d_in[0];
    const float* W_ih = (const float*)d_in[1];
    const float* W_hh = (const float*)d_in[2];
    const float* b_ih = (const float*)d_in[3];
    const float* b_hh = (const float*)d_in[4];
    const float* W_fc = (const float*)d_in[5];
    const float* b_fc = (const float*)d_in[6];
    float* out = (float*)d_out;

    prep_x_kernel<<<(BB * TT + 255) / 256, 256>>>(x);
    lstm_hmma_kernel<<<NCTA, THREADS>>>(W_ih, W_hh, b_ih, b_hh, W_fc, b_fc, out);
}

// round 17
// speedup vs baseline: 1.5767x; 1.2198x over previous
#include <cuda_runtime.h>
#include <cuda_bf16.h>
#include <cstdint>

// SimpleLSTM: B=4096, T=256, I=16, H=32, O=1 (fp32)
// R17 = R16 HMMA recurrence with NB 16 -> 8 (512 CTAs, 4 CTAs/SM):
// more independent recurrences per SM to overlap the serial chain.
// Warp w's M=32 rows -> (gate=m/8, unit=8w+m%8): all 4 gates of a unit land
// in one thread's accumulators -> in-register cell update, no exchange.
// A (bf16 hi/lo, 0.5 gate-fold) in regs; B=[h | xA | xB] smem rows [bat][72];
// 3 compensation segments (Whi*vhi + Whi*vlo + Wlo*vhi) ~ fp32 matmul.

#define BB 4096
#define TT 256
#define II 16
#define HH 32
#define NB 8
#define NCTA (BB / NB)    // 512
#define THREADS 128
#define KS 72             // padded K stride (144B rows, conflict-clean)

__device__ uint4 g_xpk[(long)BB * TT * 4];   // [b*T+t] -> {hi0,hi1,lo0,lo1}

__device__ __forceinline__ float tanh_a(float v) {
    float r; asm("tanh.approx.f32 %0, %1;" : "=f"(r) : "f"(v)); return r;
}
__device__ __forceinline__ void cp_async16(void* smem_dst, const void* gsrc) {
    unsigned a = (unsigned)__cvta_generic_to_shared(smem_dst);
    asm volatile("cp.async.ca.shared.global [%0], [%1], 16;" :: "r"(a), "l"(gsrc));
}
__device__ __forceinline__ void cp_commit() {
    asm volatile("cp.async.commit_group;" ::: "memory");
}
__device__ __forceinline__ void cp_wait0() {
    asm volatile("cp.async.wait_group 0;" ::: "memory");
}
__device__ __forceinline__ void mma_bf16(float* d, const uint32_t* a, const uint32_t* b) {
    asm volatile(
        "mma.sync.aligned.m16n8k16.row.col.f32.bf16.bf16.f32 "
        "{%0,%1,%2,%3}, {%4,%5,%6,%7}, {%8,%9}, {%0,%1,%2,%3};"
        : "+f"(d[0]), "+f"(d[1]), "+f"(d[2]), "+f"(d[3])
        : "r"(a[0]), "r"(a[1]), "r"(a[2]), "r"(a[3]), "r"(b[0]), "r"(b[1]));
}
__device__ __forceinline__ uint32_t pack_bf2(__nv_bfloat16 e0, __nv_bfloat16 e1) {
    uint16_t u0 = *reinterpret_cast<uint16_t*>(&e0);
    uint16_t u1 = *reinterpret_cast<uint16_t*>(&e1);
    return (uint32_t)u0 | ((uint32_t)u1 << 16);
}

// ---------------- prep: x -> bf16 hi/lo ----------------
__global__ void __launch_bounds__(256)
prep_x_kernel(const float* __restrict__ x) {
    const long idx = (long)blockIdx.x * 256 + threadIdx.x;   // b*T + t
    if (idx >= (long)BB * TT) return;
    const float4* src = reinterpret_cast<const float4*>(x + idx * II);
    float4 v0 = src[0], v1 = src[1], v2 = src[2], v3 = src[3];
    float v[16] = {v0.x, v0.y, v0.z, v0.w, v1.x, v1.y, v1.z, v1.w,
                   v2.x, v2.y, v2.z, v2.w, v3.x, v3.y, v3.z, v3.w};
    __nv_bfloat16 hi[16], lo[16];
    #pragma unroll
    for (int i = 0; i < 16; i++) {
        hi[i] = __float2bfloat16(v[i]);
        lo[i] = __float2bfloat16(v[i] - __bfloat162float(hi[i]));
    }
    uint4* dst = g_xpk + idx * 4;
    dst[0] = *reinterpret_cast<uint4*>(&hi[0]);
    dst[1] = *reinterpret_cast<uint4*>(&hi[8]);
    dst[2] = *reinterpret_cast<uint4*>(&lo[0]);
    dst[3] = *reinterpret_cast<uint4*>(&lo[8]);
}

// ---------------- main kernel ----------------
__global__ void __launch_bounds__(THREADS, 4)
lstm_hmma_kernel(const float* __restrict__ W_ih,   // [4H,I]
                 const float* __restrict__ W_hh,   // [4H,H]
                 const float* __restrict__ b_ih,   // [4H]
                 const float* __restrict__ b_hh,   // [4H]
                 const float* __restrict__ W_fc,   // [1,H]
                 const float* __restrict__ b_fc,   // [1]
                 float* __restrict__ out)          // [B,1]
{
    __shared__ __align__(16) __nv_bfloat16 sVh[NB][KS];   // B hi: h | xA | xB
    __shared__ __align__(16) __nv_bfloat16 sVl[NB][KS];   // B lo
    __shared__ float sRed[4][NB];

    const int tid = threadIdx.x;
    const int w   = tid >> 5;
    const int l   = tid & 31;
    const int lr  = l >> 2;     // 0..7
    const int lc  = l & 3;      // 0..3
    const int b0  = blockIdx.x * NB;

    // ---- zero B arrays (h rows start at 0) ----
    for (int i = tid; i < NB * KS * 2 / 16; i += THREADS) {
        reinterpret_cast<uint4*>(&sVh[0][0])[i] = make_uint4(0, 0, 0, 0);
        reinterpret_cast<uint4*>(&sVl[0][0])[i] = make_uint4(0, 0, 0, 0);
    }

    // ---- A fragments in registers ----
    uint32_t Ahi[2][3][4], Alo[2][3][4];
    #pragma unroll
    for (int mt = 0; mt < 2; mt++)
        #pragma unroll
        for (int kc = 0; kc < 3; kc++)
            #pragma unroll
            for (int p = 0; p < 4; p++) {
                int m    = mt * 16 + lr + ((p & 1) ? 8 : 0);
                int gate = m >> 3;
                int unit = 8 * w + (m & 7);
                int grow = gate * HH + unit;
                int k    = kc * 16 + lc * 2 + ((p & 2) ? 8 : 0);
                float s  = (gate == 2) ? 1.0f : 0.5f;
                float v0 = s * ((k < HH) ? W_hh[grow * HH + k]
                                         : W_ih[grow * II + (k - HH)]);
                float v1 = s * ((k + 1 < HH) ? W_hh[grow * HH + k + 1]
                                             : W_ih[grow * II + (k + 1 - HH)]);
                __nv_bfloat16 h0 = __float2bfloat16(v0);
                __nv_bfloat16 h1 = __float2bfloat16(v1);
                Ahi[mt][kc][p] = pack_bf2(h0, h1);
                Alo[mt][kc][p] = pack_bf2(__float2bfloat16(v0 - __bfloat162float(h0)),
                                          __float2bfloat16(v1 - __bfloat162float(h1)));
            }

    // biases for this thread's unit u = 8w+lr
    const int u = 8 * w + lr;
    float biasg[4];
    #pragma unroll
    for (int g = 0; g < 4; g++) {
        float s = (g == 2) ? 1.0f : 0.5f;
        biasg[g] = s * (b_ih[g * HH + u] + b_hh[g * HH + u]);
    }

    // ---- x(t=0) -> slot 0 (k 32..47) ----
    if (tid < 32) {
        int bat = tid >> 2, q = tid & 3;
        const uint4* src = g_xpk + ((long)(b0 + bat) * TT + 0) * 4 + q;
        char* dst = (q < 2) ? (char*)&sVh[bat][32] + q * 16
                            : (char*)&sVl[bat][32] + (q - 2) * 16;
        cp_async16(dst, src);
    }
    cp_commit();
    cp_wait0();
    __syncthreads();

    float cc2[2] = {0.f, 0.f};    // c for batches lc*2, lc*2+1 (unit u)
    float hh2[2];

    #pragma unroll 1
    for (int t = 0; t < TT; t++) {
        const int kx = 32 + 16 * (t & 1);

        // ---- load B fragments (h chunks + current x chunk), n-rows = lr ----
        uint32_t bh[3][2], bl[3][2];
        #pragma unroll
        for (int kc = 0; kc < 3; kc++) {
            const int kb = (kc < 2) ? kc * 16 : kx;
            const __nv_bfloat16* ph = &sVh[lr][kb + lc * 2];
            const __nv_bfloat16* pl = &sVl[lr][kb + lc * 2];
            bh[kc][0] = *reinterpret_cast<const uint32_t*>(ph);
            bh[kc][1] = *reinterpret_cast<const uint32_t*>(ph + 8);
            bl[kc][0] = *reinterpret_cast<const uint32_t*>(pl);
            bl[kc][1] = *reinterpret_cast<const uint32_t*>(pl + 8);
        }
        __syncthreads();   // h(t-1)+x(t) captured: h region writable

        // ---- prefetch x(t+1) into the other slot ----
        {
            const int tn = (t + 1 < TT) ? t + 1 : TT - 1;
            const int xo = 32 + 16 * ((t + 1) & 1);
            if (tid < 32) {
                int bat = tid >> 2, q = tid & 3;
                const uint4* src = g_xpk + ((long)(b0 + bat) * TT + tn) * 4 + q;
                char* dst = (q < 2) ? (char*)&sVh[bat][xo] + q * 16
                                    : (char*)&sVl[bat][xo] + (q - 2) * 16;
                cp_async16(dst, src);
            }
            cp_commit();
        }

        // ---- MMAs: acc init with bias, 3 segments x 2mt x 3kc ----
        float acc[2][4];
        #pragma unroll
        for (int mt = 0; mt < 2; mt++) {
            acc[mt][0] = biasg[mt * 2];      // gate mt*2   (row lr)
            acc[mt][1] = biasg[mt * 2];
            acc[mt][2] = biasg[mt * 2 + 1];  // gate mt*2+1 (row lr+8)
            acc[mt][3] = biasg[mt * 2 + 1];
        }
        #pragma unroll
        for (int kc = 0; kc < 3; kc++)
            #pragma unroll
            for (int mt = 0; mt < 2; mt++) {
                mma_bf16(acc[mt], Ahi[mt][kc], bh[kc]);   // hi*hi
                mma_bf16(acc[mt], Ahi[mt][kc], bl[kc]);   // hi*lo
                mma_bf16(acc[mt], Alo[mt][kc], bh[kc]);   // lo*hi
            }

        // ---- cell update (all 4 gates in-register), write h hi/lo ----
        #pragma unroll
        for (int j = 0; j < 2; j++) {
            float gi = fmaf(tanh_a(acc[0][j]),     0.5f, 0.5f);
            float gf = fmaf(tanh_a(acc[0][2 + j]), 0.5f, 0.5f);
            float gg = tanh_a(acc[1][j]);
            float go = fmaf(tanh_a(acc[1][2 + j]), 0.5f, 0.5f);
            cc2[j] = fmaf(gf, cc2[j], gi * gg);
            float hv = go * tanh_a(cc2[j]);
            hh2[j] = hv;
            const int bat = lc * 2 + j;
            __nv_bfloat16 hi = __float2bfloat16(hv);
            sVh[bat][u] = hi;
            sVl[bat][u] = __float2bfloat16(hv - __bfloat162float(hi));
        }

        cp_wait0();
        __syncthreads();   // h(t) + x(t+1) visible
    }

    // ---- final FC (O=1): reduce over units u ----
    float wfc = W_fc[u];
    float p0 = hh2[0] * wfc, p1 = hh2[1] * wfc;
    #pragma unroll
    for (int off = 4; off < 32; off <<= 1) {
        p0 += __shfl_xor_sync(0xffffffffu, p0, off);
        p1 += __shfl_xor_sync(0xffffffffu, p1, off);
    }
    if (lr == 0) {
        sRed[w][lc * 2 + 0] = p0;
        sRed[w][lc * 2 + 1] = p1;
    }
    __syncthreads();
    if (tid < NB)
        out[b0 + tid] = sRed[0][tid] + sRed[1][tid] + sRed[2][tid] + sRed[3][tid]
                      + b_fc[0];
}

extern "C" void kernel_launch(void* const* d_in, const int* in_sizes, int n_in,
                              void* d_out, int out_size) {
    (void)in_sizes; (void)n_in; (void)out_size;
    const float* x    = (const float*)d_in[0];
    const float* W_ih = (const float*)d_in[1];
    const float* W_hh = (const float*)d_in[2];
    const float* b_ih = (const float*)d_in[3];
    const float* b_hh = (const float*)d_in[4];
    const float* W_fc = (const float*)d_in[5];
    const float* b_fc = (const float*)d_in[6];
    float* out = (float*)d_out;

    prep_x_kernel<<<(BB * TT + 255) / 256, 256>>>(x);
    lstm_hmma_kernel<<<NCTA, THREADS>>>(W_ih, W_hh, b_ih, b_hh, W_fc, b_fc, out);
}